// round 9
// baseline (speedup 1.0000x reference)
#include <cuda_runtime.h>
#include <cstdint>

#define HD   512
#define SEQT 4096
#define G3   1536
#define REC_CTAS 128           // 64 per sequence
#define GEMM_CTAS 20
#define NUNITS (GEMM_CTAS * 2)
#define NTILES (128 * 24)

// ---------------- static device scratch (no cudaMalloc allowed) -------------
__device__ __align__(16) float g_GI[2][SEQT][G3];   // precomputed input gates (~50MB)
__device__ unsigned long long g_htag[2][2][HD];     // {tag,val}, [buf][seq][i]
__device__ unsigned g_cnt[128];                     // per row-tile completion counters
__device__ float g_h1[HD], g_h2[HD];                // sentence-GRU intermediates
__device__ float g_sink;                            // prefetch sink (never read)

// ---------------- memory helpers --------------------------------------------
__device__ __forceinline__ unsigned ld_acq_u32(const unsigned* p) {
    unsigned v; asm volatile("ld.acquire.gpu.global.u32 %0,[%1];" : "=r"(v) : "l"(p)); return v;
}
__device__ __forceinline__ void red_rel_add(unsigned* p, unsigned v) {
    asm volatile("red.release.gpu.global.add.u32 [%0],%1;" :: "l"(p), "r"(v) : "memory");
}
__device__ __forceinline__ unsigned long long ld_rlx_u64(const unsigned long long* p) {
    unsigned long long v; asm volatile("ld.relaxed.gpu.global.b64 %0,[%1];" : "=l"(v) : "l"(p)); return v;
}
__device__ __forceinline__ void st_rlx_u64(unsigned long long* p, unsigned long long v) {
    asm volatile("st.relaxed.gpu.global.b64 [%0],%1;" :: "l"(p), "l"(v) : "memory");
}
__device__ __forceinline__ void fence_gpu() {
    asm volatile("fence.acq_rel.gpu;" ::: "memory");
}
__device__ __forceinline__ void bar_named(int id, int cnt) {
    asm volatile("bar.sync %0, %1;" :: "r"(id), "r"(cnt) : "memory");
}

// HW tanh (MUFU.TANH) — validated rel_err 0.0 since R4
__device__ __forceinline__ float tanha(float x) {
    float y; asm("tanh.approx.f32 %0,%1;" : "=f"(y) : "f"(x)); return y;
}
__device__ __forceinline__ float sigf(float x) {       // sig(x)=0.5*tanh(x/2)+0.5
    return fmaf(0.5f, tanha(0.5f * x), 0.5f);
}
__device__ __forceinline__ float wredu(float v) {
#pragma unroll
    for (int o = 16; o; o >>= 1) v += __shfl_xor_sync(0xffffffffu, v, o);
    return v;
}

// ---------------------------------------------------------------------------
// Kernel 0: reset tags + GI counters (runs every graph replay)
// ---------------------------------------------------------------------------
__global__ void init_kernel() {
    int i = blockIdx.x * blockDim.x + threadIdx.x;
    if (i < 2 * 2 * HD) ((unsigned long long*)g_htag)[i] = 0ull;   // tag 0 never matches
    if (i < 128) g_cnt[i] = 0u;
}

// ---------------------------------------------------------------------------
// Fused kernel: 148 CTAs x 512 threads.
//   CTAs [0,128):  persistent GRU recurrence:
//                  seq = bx>>6, c = bx&63 owns h[8c..8c+8).
//                  EVERY thread polls one 8B tag word into double-buffered
//                  sm_h (R4/R8 validated scheme, no dedicated spinners).
//                  Warps 0-7: warp q owns h index 8c+q with ALL THREE gate
//                  rows (48 weight regs; 512-thread launch bounds -> 128-reg
//                  budget, no spill). In-warp reduce yields r,z,n -> lane 0
//                  gates + publishes its own 8B word. ONE barrier per step;
//                  sm_gh and bar(B) eliminated.
//   CTAs [128,148): 2 x 256-thread GEMM units each, producing GI row-tiles,
//                  then prefetching tail weights into L2.
// ---------------------------------------------------------------------------
__global__ void __launch_bounds__(512, 1)
fused_kernel(const int* __restrict__ xs, const int* __restrict__ ys,
             const float* __restrict__ emb,
             const float* __restrict__ Wih, const float* __restrict__ bih,
             const float* __restrict__ Whh, const float* __restrict__ bhh,
             const float* __restrict__ Wih2, const float* __restrict__ Whh2,
             const float* __restrict__ W1) {
    const int tid = threadIdx.x;

    if (blockIdx.x >= REC_CTAS) {
        // ================== GEMM producer (R8, unchanged) ==================
        __shared__ __align__(16) float pool[2 * 2048];
        const int gidx = tid >> 8;            // 0..1
        const int tidl = tid & 255;
        const int barid = gidx + 1;           // named barriers 1..2
        float* As = pool + gidx * 2048;
        float* Bs = As + 1024;

        const int tr = (tidl >> 4) << 2;
        const int tc = (tidl & 15) << 2;
        const int lr = tidl >> 2;
        const int kv = (tidl & 3) << 2;

        const int unit = (blockIdx.x - REC_CTAS) * 2 + gidx;

        for (int T = unit; T < NTILES; T += NUNITS) {
            const int e  = T / 24;
            const int cc = T - e * 24;
            const int xy = e & 1;
            const int trow = (e >> 1) << 6;
            const int col0 = cc << 6;

            const int tok = (xy ? ys : xs)[trow + lr];
            const float* arow = emb + (size_t)tok * HD;
            const float* brow = Wih + (size_t)(col0 + lr) * HD;

            float acc[4][4];
#pragma unroll
            for (int i = 0; i < 4; i++)
#pragma unroll
                for (int j = 0; j < 4; j++) acc[i][j] = 0.0f;

            for (int k0 = 0; k0 < HD; k0 += 16) {
                float4 a4 = *(const float4*)(arow + k0 + kv);
                float4 b4 = *(const float4*)(brow + k0 + kv);
                As[(kv + 0) * 64 + lr] = a4.x; As[(kv + 1) * 64 + lr] = a4.y;
                As[(kv + 2) * 64 + lr] = a4.z; As[(kv + 3) * 64 + lr] = a4.w;
                Bs[(kv + 0) * 64 + lr] = b4.x; Bs[(kv + 1) * 64 + lr] = b4.y;
                Bs[(kv + 2) * 64 + lr] = b4.z; Bs[(kv + 3) * 64 + lr] = b4.w;
                bar_named(barid, 256);
#pragma unroll
                for (int k = 0; k < 16; k++) {
                    float4 av = *(const float4*)&As[k * 64 + tr];
                    float4 bv = *(const float4*)&Bs[k * 64 + tc];
                    acc[0][0] = fmaf(av.x, bv.x, acc[0][0]);
                    acc[0][1] = fmaf(av.x, bv.y, acc[0][1]);
                    acc[0][2] = fmaf(av.x, bv.z, acc[0][2]);
                    acc[0][3] = fmaf(av.x, bv.w, acc[0][3]);
                    acc[1][0] = fmaf(av.y, bv.x, acc[1][0]);
                    acc[1][1] = fmaf(av.y, bv.y, acc[1][1]);
                    acc[1][2] = fmaf(av.y, bv.z, acc[1][2]);
                    acc[1][3] = fmaf(av.y, bv.w, acc[1][3]);
                    acc[2][0] = fmaf(av.z, bv.x, acc[2][0]);
                    acc[2][1] = fmaf(av.z, bv.y, acc[2][1]);
                    acc[2][2] = fmaf(av.z, bv.z, acc[2][2]);
                    acc[2][3] = fmaf(av.z, bv.w, acc[2][3]);
                    acc[3][0] = fmaf(av.w, bv.x, acc[3][0]);
                    acc[3][1] = fmaf(av.w, bv.y, acc[3][1]);
                    acc[3][2] = fmaf(av.w, bv.z, acc[3][2]);
                    acc[3][3] = fmaf(av.w, bv.w, acc[3][3]);
                }
                bar_named(barid, 256);
            }

            float4 bias = *(const float4*)(bih + col0 + tc);
#pragma unroll
            for (int ii = 0; ii < 4; ii++) {
                float4 v;
                v.x = acc[ii][0] + bias.x;
                v.y = acc[ii][1] + bias.y;
                v.z = acc[ii][2] + bias.z;
                v.w = acc[ii][3] + bias.w;
                *(float4*)&g_GI[xy][trow + tr + ii][col0 + tc] = v;
            }
            bar_named(barid, 256);
            if (tidl == 0) {
                fence_gpu();
                red_rel_add(&g_cnt[e], 1u);
            }
        }

        // ---- warm L2 with tail weights
        {
            const int nthr = GEMM_CTAS * 512;
            const int gt = (blockIdx.x - REC_CTAS) * 512 + tid;
            float s = 0.0f;
            const int n4 = (G3 * HD) / 4;
            for (int i = gt; i < n4; i += nthr) {
                float4 a = __ldcg((const float4*)Wih2 + i);
                float4 b = __ldcg((const float4*)Whh2 + i);
                s += a.x + a.w + b.x + b.w;
            }
            const int m4 = (128 * HD) / 4;
            for (int i = gt; i < m4; i += nthr) {
                float4 a = __ldcg((const float4*)W1 + i);
                s += a.x + a.w;
            }
            if (s == 1.2345678e38f) g_sink = s;    // never true; defeats DCE
        }
        return;
    }

    // ================== GRU recurrence (one sequence per CTA group) =========
    const int seq = blockIdx.x >> 6;          // 0 = x, 1 = y
    const int c   = blockIdx.x & 63;          // owns h indices [8c, 8c+8)
    const int w    = tid >> 5;                // 16 warps
    const int lane = tid & 31;

    __shared__ __align__(16) float sm_h[2][HD];   // double-buffered staged h

    // dot warps (w < 8): warp w owns h index i8 with rows {r,z,n}.
    // Weight mapping matches the float4 h read: column 4*lane + 128*k + e.
    const int i8 = (c << 3) + (w & 7);
    float wr_[16], wz_[16], wn_[16];
    float bhr = 0.f, bhz = 0.f, bhn = 0.f;
    if (w < 8) {
#pragma unroll
        for (int k = 0; k < 4; k++) {
            float4 vr = *(const float4*)&Whh[(size_t)i8 * HD + 4 * lane + 128 * k];
            float4 vz = *(const float4*)&Whh[(size_t)(512 + i8) * HD + 4 * lane + 128 * k];
            float4 vn = *(const float4*)&Whh[(size_t)(1024 + i8) * HD + 4 * lane + 128 * k];
            wr_[4 * k + 0] = vr.x; wr_[4 * k + 1] = vr.y;
            wr_[4 * k + 2] = vr.z; wr_[4 * k + 3] = vr.w;
            wz_[4 * k + 0] = vz.x; wz_[4 * k + 1] = vz.y;
            wz_[4 * k + 2] = vz.z; wz_[4 * k + 3] = vz.w;
            wn_[4 * k + 0] = vn.x; wn_[4 * k + 1] = vn.y;
            wn_[4 * k + 2] = vn.z; wn_[4 * k + 3] = vn.w;
        }
        bhr = bhh[i8]; bhz = bhh[512 + i8]; bhn = bhh[1024 + i8];
    }

    for (int t = 0; t < SEQT; t++) {
        const int buf = t & 1;

        // ---- GI readiness (one counter for this seq, every 64 steps) ----
        if ((t & 63) == 0) {
            if (tid == 0) {
                const int e = ((t >> 6) << 1) + seq;
                while (ld_acq_u32(&g_cnt[e]) < 24u) { }
            }
            __syncthreads();
        }

        // ---- GI prefetch (lane 0 of dot warps; hides under the poll) ----
        float gr = 0.f, gz = 0.f, gn = 0.f;
        if (w < 8 && lane == 0) {
            const float* GI = &g_GI[seq][t][0];
            gr = GI[i8]; gz = GI[512 + i8]; gn = GI[1024 + i8];
        }

        // ---- stage h: every thread polls exactly one tag word (R4/R8) ----
        {
            float hv;
            if (t == 0) {
                hv = 0.0f;
            } else {
                const unsigned long long* pp = &g_htag[buf][seq][tid];
                unsigned long long a = ld_rlx_u64(pp);
                while ((unsigned)(a >> 32) != (unsigned)t) a = ld_rlx_u64(pp);
                hv = __uint_as_float((unsigned)a);
            }
            sm_h[buf][tid] = hv;
        }
        __syncthreads();                       // the ONLY barrier per step

        // ---- fused dot + gates + publish, 3 rows per warp ----
        if (w < 8) {
            const float4* hb4 = (const float4*)sm_h[buf];
            float ar = 0.f, az = 0.f, an = 0.f;
#pragma unroll
            for (int k = 0; k < 4; k++) {
                float4 h4 = hb4[lane + 32 * k];
                ar = fmaf(wr_[4 * k + 0], h4.x, ar);
                az = fmaf(wz_[4 * k + 0], h4.x, az);
                an = fmaf(wn_[4 * k + 0], h4.x, an);
                ar = fmaf(wr_[4 * k + 1], h4.y, ar);
                az = fmaf(wz_[4 * k + 1], h4.y, az);
                an = fmaf(wn_[4 * k + 1], h4.y, an);
                ar = fmaf(wr_[4 * k + 2], h4.z, ar);
                az = fmaf(wz_[4 * k + 2], h4.z, az);
                an = fmaf(wn_[4 * k + 2], h4.z, an);
                ar = fmaf(wr_[4 * k + 3], h4.w, ar);
                az = fmaf(wz_[4 * k + 3], h4.w, az);
                an = fmaf(wn_[4 * k + 3], h4.w, an);
            }
#pragma unroll
            for (int o = 16; o; o >>= 1) {
                ar += __shfl_xor_sync(0xffffffffu, ar, o);
                az += __shfl_xor_sync(0xffffffffu, az, o);
                an += __shfl_xor_sync(0xffffffffu, an, o);
            }
            if (lane == 0) {
                float r = sigf(gr + ar + bhr);
                float z = sigf(gz + az + bhz);
                float n = tanha(gn + r * (an + bhn));
                float hn = n + z * (sm_h[buf][i8] - n);
                st_rlx_u64(&g_htag[(t + 1) & 1][seq][i8],
                           (((unsigned long long)(unsigned)(t + 1)) << 32) |
                           (unsigned long long)__float_as_uint(hn));
            }
        }
        // Hazard proof (single barrier + double buffer):
        //  - pollers write sm_h[t&1] before bar(t); dot warps read after bar(t).
        //  - next write to sm_h[t&1] is at iteration t+2, which every thread
        //    reaches only after bar(t+1); each dot warp arrives at bar(t+1)
        //    only after completing ALL its step-t reads (dot + sm_h[i8]).
        //  - remote h values travel inside the same 8B word as their tag.
    }
}

// ---------------------------------------------------------------------------
// Tail A: sentence-GRU step 1 (input hidden_x, h_prev = 0). 128 CTAs x 128.
// ---------------------------------------------------------------------------
__global__ void __launch_bounds__(128) tailA(const float* __restrict__ Wih2,
                                             const float* __restrict__ bih2,
                                             const float* __restrict__ bhh2) {
    __shared__ float sx[HD];
    const int tid = threadIdx.x, w = tid >> 5, lane = tid & 31;
    for (int i = tid; i < HD; i += 128)
        sx[i] = __uint_as_float((unsigned)g_htag[0][0][i]);
    __syncthreads();

    const int i = blockIdx.x * 4 + w;
    float ar = 0.f, az = 0.f, an = 0.f;
    for (int k = 0; k < 16; k++) {
        int j = lane + 32 * k;
        float h = sx[j];
        ar = fmaf(Wih2[(size_t)i * HD + j], h, ar);
        az = fmaf(Wih2[(size_t)(512 + i) * HD + j], h, az);
        an = fmaf(Wih2[(size_t)(1024 + i) * HD + j], h, an);
    }
    ar = wredu(ar); az = wredu(az); an = wredu(an);
    if (lane == 0) {
        float r = sigf(ar + bih2[i] + bhh2[i]);
        float z = sigf(az + bih2[512 + i] + bhh2[512 + i]);
        float n = tanha(an + bih2[1024 + i] + r * bhh2[1024 + i]);
        g_h1[i] = (1.0f - z) * n;
    }
}

// ---------------------------------------------------------------------------
// Tail B: sentence-GRU step 2 (input hidden_y, h_prev = h1). 128 CTAs x 128.
// ---------------------------------------------------------------------------
__global__ void __launch_bounds__(128) tailB(const float* __restrict__ Wih2,
                                             const float* __restrict__ Whh2,
                                             const float* __restrict__ bih2,
                                             const float* __restrict__ bhh2) {
    __shared__ float sy[HD], s1[HD];
    const int tid = threadIdx.x, w = tid >> 5, lane = tid & 31;
    for (int i = tid; i < HD; i += 128) {
        sy[i] = __uint_as_float((unsigned)g_htag[0][1][i]);
        s1[i] = g_h1[i];
    }
    __syncthreads();

    const int i = blockIdx.x * 4 + w;
    float ir = 0.f, iz = 0.f, in_ = 0.f, hr = 0.f, hz = 0.f, hn_ = 0.f;
    for (int k = 0; k < 16; k++) {
        int j = lane + 32 * k;
        float hy = sy[j], h1 = s1[j];
        size_t r0 = (size_t)i * HD + j;
        size_t r1 = (size_t)(512 + i) * HD + j;
        size_t r2 = (size_t)(1024 + i) * HD + j;
        ir = fmaf(Wih2[r0], hy, ir);   hr = fmaf(Whh2[r0], h1, hr);
        iz = fmaf(Wih2[r1], hy, iz);   hz = fmaf(Whh2[r1], h1, hz);
        in_ = fmaf(Wih2[r2], hy, in_); hn_ = fmaf(Whh2[r2], h1, hn_);
    }
    ir = wredu(ir); iz = wredu(iz); in_ = wredu(in_);
    hr = wredu(hr); hz = wredu(hz); hn_ = wredu(hn_);
    if (lane == 0) {
        float r = sigf(ir + bih2[i] + hr + bhh2[i]);
        float z = sigf(iz + bih2[512 + i] + hz + bhh2[512 + i]);
        float n = tanha(in_ + bih2[1024 + i] + r * (hn_ + bhh2[1024 + i]));
        g_h2[i] = n + z * (s1[i] - n);
    }
}

// ---------------------------------------------------------------------------
// Tail C: MLP + log_softmax. 1 CTA x 1024.
// ---------------------------------------------------------------------------
__global__ void __launch_bounds__(1024) tailC(const float* __restrict__ W1,
                                              const float* __restrict__ b1,
                                              const float* __restrict__ W2,
                                              const float* __restrict__ b2,
                                              float* __restrict__ out) {
    __shared__ float s2[HD], m1[128];
    const int tid = threadIdx.x, w = tid >> 5, lane = tid & 31;
    if (tid < HD) s2[tid] = g_h2[tid];
    __syncthreads();

    const int r0 = w * 4;
    float acc[4] = {0.f, 0.f, 0.f, 0.f};
    for (int k = 0; k < 16; k++) {
        int j = lane + 32 * k;
        float h = s2[j];
#pragma unroll
        for (int q = 0; q < 4; q++)
            acc[q] = fmaf(W1[(size_t)(r0 + q) * HD + j], h, acc[q]);
    }
#pragma unroll
    for (int q = 0; q < 4; q++) acc[q] = wredu(acc[q]);
    if (lane == 0) {
#pragma unroll
        for (int q = 0; q < 4; q++)
            m1[r0 + q] = fmaxf(acc[q] + b1[r0 + q], 0.0f);
    }
    __syncthreads();

    if (w == 0) {
        float a0 = 0.f, a1 = 0.f;
        for (int k = 0; k < 4; k++) {
            int j = lane + 32 * k;
            a0 = fmaf(W2[j], m1[j], a0);
            a1 = fmaf(W2[128 + j], m1[j], a1);
        }
        a0 = wredu(a0);
        a1 = wredu(a1);
        if (lane == 0) {
            float v0 = fmaxf(a0 + b2[0], 0.0f);
            float v1 = fmaxf(a1 + b2[1], 0.0f);
            float m = fmaxf(v0, v1);
            float lse = m + logf(expf(v0 - m) + expf(v1 - m));
            out[0] = v0 - lse;
            out[1] = v1 - lse;
        }
    }
}

// ---------------------------------------------------------------------------
extern "C" void kernel_launch(void* const* d_in, const int* in_sizes, int n_in,
                              void* d_out, int out_size) {
    const int*   x    = (const int*)d_in[0];
    const int*   y    = (const int*)d_in[1];
    const float* emb  = (const float*)d_in[2];
    const float* Wih1 = (const float*)d_in[3];
    const float* Whh1 = (const float*)d_in[4];
    const float* bih1 = (const float*)d_in[5];
    const float* bhh1 = (const float*)d_in[6];
    const float* Wih2 = (const float*)d_in[7];
    const float* Whh2 = (const float*)d_in[8];
    const float* bih2 = (const float*)d_in[9];
    const float* bhh2 = (const float*)d_in[10];
    const float* W1   = (const float*)d_in[11];
    const float* b1   = (const float*)d_in[12];
    const float* W2   = (const float*)d_in[13];
    const float* b2   = (const float*)d_in[14];
    float* out = (float*)d_out;

    init_kernel<<<2, 1024>>>();
    fused_kernel<<<REC_CTAS + GEMM_CTAS, 512>>>(x, y, emb, Wih1, bih1, Whh1, bhh1,
                                                Wih2, Whh2, W1);
    tailA<<<128, 128>>>(Wih2, bih2, bhh2);
    tailB<<<128, 128>>>(Wih2, Whh2, bih2, bhh2);
    tailC<<<1, 1024>>>(W1, b1, W2, b2, out);
}

// round 10
// speedup vs baseline: 1.4301x; 1.4301x over previous
#include <cuda_runtime.h>
#include <cstdint>

#define HD   512
#define SEQT 4096
#define G3   1536
#define REC_CTAS 128           // 64 per sequence
#define GEMM_CTAS 20
#define NUNITS (GEMM_CTAS * 2)
#define NTILES (128 * 24)

// ---------------- static device scratch (no cudaMalloc allowed) -------------
__device__ __align__(16) float g_GI[2][SEQT][G3];   // precomputed input gates (~50MB)
__device__ unsigned long long g_htag[2][2][HD];     // {tag,val}, [buf][seq][i]
__device__ unsigned g_cnt[128];                     // per row-tile completion counters
__device__ float g_h1[HD], g_h2[HD];                // sentence-GRU intermediates
__device__ float g_sink;                            // prefetch sink (never read)

// ---------------- memory helpers --------------------------------------------
__device__ __forceinline__ unsigned ld_acq_u32(const unsigned* p) {
    unsigned v; asm volatile("ld.acquire.gpu.global.u32 %0,[%1];" : "=r"(v) : "l"(p)); return v;
}
__device__ __forceinline__ void red_rel_add(unsigned* p, unsigned v) {
    asm volatile("red.release.gpu.global.add.u32 [%0],%1;" :: "l"(p), "r"(v) : "memory");
}
__device__ __forceinline__ unsigned long long ld_rlx_u64(const unsigned long long* p) {
    unsigned long long v; asm volatile("ld.relaxed.gpu.global.b64 %0,[%1];" : "=l"(v) : "l"(p)); return v;
}
__device__ __forceinline__ void st_rlx_u64(unsigned long long* p, unsigned long long v) {
    asm volatile("st.relaxed.gpu.global.b64 [%0],%1;" :: "l"(p), "l"(v) : "memory");
}
__device__ __forceinline__ void fence_gpu() {
    asm volatile("fence.acq_rel.gpu;" ::: "memory");
}
__device__ __forceinline__ void bar_named(int id, int cnt) {
    asm volatile("bar.sync %0, %1;" :: "r"(id), "r"(cnt) : "memory");
}

// HW tanh (MUFU.TANH) — validated rel_err 0.0 since R4
__device__ __forceinline__ float tanha(float x) {
    float y; asm("tanh.approx.f32 %0,%1;" : "=f"(y) : "f"(x)); return y;
}
__device__ __forceinline__ float sigf(float x) {       // sig(x)=0.5*tanh(x/2)+0.5
    return fmaf(0.5f, tanha(0.5f * x), 0.5f);
}
__device__ __forceinline__ float wredu(float v) {
#pragma unroll
    for (int o = 16; o; o >>= 1) v += __shfl_xor_sync(0xffffffffu, v, o);
    return v;
}

// ---------------------------------------------------------------------------
// Kernel 0: reset tags + GI counters (runs every graph replay)
// ---------------------------------------------------------------------------
__global__ void init_kernel() {
    int i = blockIdx.x * blockDim.x + threadIdx.x;
    if (i < 2 * 2 * HD) ((unsigned long long*)g_htag)[i] = 0ull;   // tag 0 never matches
    if (i < 128) g_cnt[i] = 0u;
}

// ---------------------------------------------------------------------------
// Fused kernel: 148 CTAs x 512 threads.
//   CTAs [0,128):  persistent GRU recurrence (R8 frozen topology):
//                  seq = bx>>6, c = bx&63 owns h[8c..8c+8).
//                  Every thread polls ONE 8B tag word — now with a 3-deep
//                  PIPELINED spin (independent same-address loads; per-
//                  location coherence makes checking the oldest safe) ->
//                  sampling period ~260/3 cyc instead of ~270.
//                  Warps 0-11: 2 gate rows each, vectorized LDS.128 dot.
//                  Publish: warp0 lanes 0-7, ONE coalesced 64B store.
//   CTAs [128,148): 2 x 256-thread GEMM units each, producing GI row-tiles,
//                  then prefetching tail weights into L2.
// ---------------------------------------------------------------------------
__global__ void __launch_bounds__(512, 1)
fused_kernel(const int* __restrict__ xs, const int* __restrict__ ys,
             const float* __restrict__ emb,
             const float* __restrict__ Wih, const float* __restrict__ bih,
             const float* __restrict__ Whh, const float* __restrict__ bhh,
             const float* __restrict__ Wih2, const float* __restrict__ Whh2,
             const float* __restrict__ W1) {
    const int tid = threadIdx.x;

    if (blockIdx.x >= REC_CTAS) {
        // ================== GEMM producer (R8, unchanged) ==================
        __shared__ __align__(16) float pool[2 * 2048];
        const int gidx = tid >> 8;            // 0..1
        const int tidl = tid & 255;
        const int barid = gidx + 1;           // named barriers 1..2
        float* As = pool + gidx * 2048;
        float* Bs = As + 1024;

        const int tr = (tidl >> 4) << 2;
        const int tc = (tidl & 15) << 2;
        const int lr = tidl >> 2;
        const int kv = (tidl & 3) << 2;

        const int unit = (blockIdx.x - REC_CTAS) * 2 + gidx;

        for (int T = unit; T < NTILES; T += NUNITS) {
            const int e  = T / 24;
            const int cc = T - e * 24;
            const int xy = e & 1;
            const int trow = (e >> 1) << 6;
            const int col0 = cc << 6;

            const int tok = (xy ? ys : xs)[trow + lr];
            const float* arow = emb + (size_t)tok * HD;
            const float* brow = Wih + (size_t)(col0 + lr) * HD;

            float acc[4][4];
#pragma unroll
            for (int i = 0; i < 4; i++)
#pragma unroll
                for (int j = 0; j < 4; j++) acc[i][j] = 0.0f;

            for (int k0 = 0; k0 < HD; k0 += 16) {
                float4 a4 = *(const float4*)(arow + k0 + kv);
                float4 b4 = *(const float4*)(brow + k0 + kv);
                As[(kv + 0) * 64 + lr] = a4.x; As[(kv + 1) * 64 + lr] = a4.y;
                As[(kv + 2) * 64 + lr] = a4.z; As[(kv + 3) * 64 + lr] = a4.w;
                Bs[(kv + 0) * 64 + lr] = b4.x; Bs[(kv + 1) * 64 + lr] = b4.y;
                Bs[(kv + 2) * 64 + lr] = b4.z; Bs[(kv + 3) * 64 + lr] = b4.w;
                bar_named(barid, 256);
#pragma unroll
                for (int k = 0; k < 16; k++) {
                    float4 av = *(const float4*)&As[k * 64 + tr];
                    float4 bv = *(const float4*)&Bs[k * 64 + tc];
                    acc[0][0] = fmaf(av.x, bv.x, acc[0][0]);
                    acc[0][1] = fmaf(av.x, bv.y, acc[0][1]);
                    acc[0][2] = fmaf(av.x, bv.z, acc[0][2]);
                    acc[0][3] = fmaf(av.x, bv.w, acc[0][3]);
                    acc[1][0] = fmaf(av.y, bv.x, acc[1][0]);
                    acc[1][1] = fmaf(av.y, bv.y, acc[1][1]);
                    acc[1][2] = fmaf(av.y, bv.z, acc[1][2]);
                    acc[1][3] = fmaf(av.y, bv.w, acc[1][3]);
                    acc[2][0] = fmaf(av.z, bv.x, acc[2][0]);
                    acc[2][1] = fmaf(av.z, bv.y, acc[2][1]);
                    acc[2][2] = fmaf(av.z, bv.z, acc[2][2]);
                    acc[2][3] = fmaf(av.z, bv.w, acc[2][3]);
                    acc[3][0] = fmaf(av.w, bv.x, acc[3][0]);
                    acc[3][1] = fmaf(av.w, bv.y, acc[3][1]);
                    acc[3][2] = fmaf(av.w, bv.z, acc[3][2]);
                    acc[3][3] = fmaf(av.w, bv.w, acc[3][3]);
                }
                bar_named(barid, 256);
            }

            float4 bias = *(const float4*)(bih + col0 + tc);
#pragma unroll
            for (int ii = 0; ii < 4; ii++) {
                float4 v;
                v.x = acc[ii][0] + bias.x;
                v.y = acc[ii][1] + bias.y;
                v.z = acc[ii][2] + bias.z;
                v.w = acc[ii][3] + bias.w;
                *(float4*)&g_GI[xy][trow + tr + ii][col0 + tc] = v;
            }
            bar_named(barid, 256);
            if (tidl == 0) {
                fence_gpu();
                red_rel_add(&g_cnt[e], 1u);
            }
        }

        // ---- warm L2 with tail weights
        {
            const int nthr = GEMM_CTAS * 512;
            const int gt = (blockIdx.x - REC_CTAS) * 512 + tid;
            float s = 0.0f;
            const int n4 = (G3 * HD) / 4;
            for (int i = gt; i < n4; i += nthr) {
                float4 a = __ldcg((const float4*)Wih2 + i);
                float4 b = __ldcg((const float4*)Whh2 + i);
                s += a.x + a.w + b.x + b.w;
            }
            const int m4 = (128 * HD) / 4;
            for (int i = gt; i < m4; i += nthr) {
                float4 a = __ldcg((const float4*)W1 + i);
                s += a.x + a.w;
            }
            if (s == 1.2345678e38f) g_sink = s;    // never true; defeats DCE
        }
        return;
    }

    // ================== GRU recurrence (one sequence per CTA group) =========
    const int seq = blockIdx.x >> 6;          // 0 = x, 1 = y
    const int c   = blockIdx.x & 63;          // owns h indices [8c, 8c+8)
    const int w    = tid >> 5;                // 16 warps
    const int lane = tid & 31;

    __shared__ __align__(16) float sm_h[HD];
    __shared__ float sm_gh[24];

    // dot warps (w < 12): rows lr0=2w, lr1=2w+1 of 24 (row lr: gate lr>>3,
    // local h idx lr&7). Weight mapping matches the float4 h read.
    const int lr0 = 2 * w, lr1 = 2 * w + 1;
    const int g0r = ((lr0 >> 3) << 9) + (c << 3) + (lr0 & 7);
    const int g1r = ((lr1 >> 3) << 9) + (c << 3) + (lr1 & 7);

    float wa[16], wb[16];
    float bh0 = 0.f, bh1 = 0.f;
    if (w < 12) {
#pragma unroll
        for (int k = 0; k < 4; k++) {
            float4 va = *(const float4*)&Whh[(size_t)g0r * HD + 4 * lane + 128 * k];
            float4 vb = *(const float4*)&Whh[(size_t)g1r * HD + 4 * lane + 128 * k];
            wa[4 * k + 0] = va.x; wa[4 * k + 1] = va.y;
            wa[4 * k + 2] = va.z; wa[4 * k + 3] = va.w;
            wb[4 * k + 0] = vb.x; wb[4 * k + 1] = vb.y;
            wb[4 * k + 2] = vb.z; wb[4 * k + 3] = vb.w;
        }
        bh0 = bhh[g0r];
        bh1 = bhh[g1r];
    }
    const int i8 = (c << 3) + tid;            // owned h index (tid < 8)

    for (int t = 0; t < SEQT; t++) {
        // ---- GI readiness (one counter for this seq, every 64 steps) ----
        if ((t & 63) == 0) {
            if (tid == 0) {
                const int e = ((t >> 6) << 1) + seq;
                while (ld_acq_u32(&g_cnt[e]) < 24u) { }
            }
            __syncthreads();
        }

        // ---- GI prefetch (latency hides under the h poll) ----
        float gr, gz, gn;
        if (tid < 8) {
            const float* GI = &g_GI[seq][t][0];
            gr = GI[i8]; gz = GI[512 + i8]; gn = GI[1024 + i8];
        }

        // ---- stage h: one tag word per thread, 3-deep PIPELINED spin ----
        {
            float hv;
            if (t == 0) {
                hv = 0.0f;
            } else {
                const unsigned long long* pp = &g_htag[t & 1][seq][tid];
                unsigned long long a = ld_rlx_u64(pp);
                if ((unsigned)(a >> 32) != (unsigned)t) {
                    // keep 3 independent same-address loads in flight;
                    // checking the OLDEST is safe (per-location coherence:
                    // older loads never return newer values than later ones,
                    // and tag+value travel in the same 8B word).
                    unsigned long long b = ld_rlx_u64(pp);
                    unsigned long long d = ld_rlx_u64(pp);
                    do {
                        a = b; b = d; d = ld_rlx_u64(pp);
                    } while ((unsigned)(a >> 32) != (unsigned)t);
                }
                hv = __uint_as_float((unsigned)a);
            }
            sm_h[tid] = hv;
        }
        __syncthreads();                       // (A)

        // ---- gate threads: prefetch own h early (off the gate chain) ----
        float hold = 0.0f;
        if (tid < 8) hold = sm_h[i8];

        // ---- 2 gate rows per warp, vectorized h reads ----
        if (w < 12) {
            const float4* hb4 = (const float4*)sm_h;
            float a0 = 0.f, a1 = 0.f;
#pragma unroll
            for (int k = 0; k < 4; k++) {
                float4 h4 = hb4[lane + 32 * k];
                a0 = fmaf(wa[4 * k + 0], h4.x, a0);
                a1 = fmaf(wb[4 * k + 0], h4.x, a1);
                a0 = fmaf(wa[4 * k + 1], h4.y, a0);
                a1 = fmaf(wb[4 * k + 1], h4.y, a1);
                a0 = fmaf(wa[4 * k + 2], h4.z, a0);
                a1 = fmaf(wb[4 * k + 2], h4.z, a1);
                a0 = fmaf(wa[4 * k + 3], h4.w, a0);
                a1 = fmaf(wb[4 * k + 3], h4.w, a1);
            }
#pragma unroll
            for (int o = 16; o; o >>= 1) {
                a0 += __shfl_xor_sync(0xffffffffu, a0, o);
                a1 += __shfl_xor_sync(0xffffffffu, a1, o);
            }
            if (lane == 0) {
                sm_gh[lr0] = a0 + bh0;
                sm_gh[lr1] = a1 + bh1;
            }
        }
        __syncthreads();                       // (B)

        // ---- gates + publish: warp 0 lanes 0-7, ONE coalesced 64B store ----
        if (tid < 8) {
            float r = sigf(gr + sm_gh[tid]);
            float z = sigf(gz + sm_gh[8 + tid]);
            float n = tanha(gn + r * sm_gh[16 + tid]);
            float hn = n + z * (hold - n);
            st_rlx_u64(&g_htag[(t + 1) & 1][seq][i8],
                       (((unsigned long long)(unsigned)(t + 1)) << 32) |
                       (unsigned long long)__float_as_uint(hn));
        }
        // Hazard proof (identical to R8):
        //  - sm_h overwrites at t+1 happen after bar(B,t); all reads of
        //    sm_h(t) (dot + hold prefetch) precede bar(B,t).
        //  - sm_gh(t) reads by gate threads precede their own arrival at
        //    bar(A,t+1), which gates any sm_gh rewrite.
    }
}

// ---------------------------------------------------------------------------
// Tail A: sentence-GRU step 1 (input hidden_x, h_prev = 0). 128 CTAs x 128.
// ---------------------------------------------------------------------------
__global__ void __launch_bounds__(128) tailA(const float* __restrict__ Wih2,
                                             const float* __restrict__ bih2,
                                             const float* __restrict__ bhh2) {
    __shared__ float sx[HD];
    const int tid = threadIdx.x, w = tid >> 5, lane = tid & 31;
    for (int i = tid; i < HD; i += 128)
        sx[i] = __uint_as_float((unsigned)g_htag[0][0][i]);
    __syncthreads();

    const int i = blockIdx.x * 4 + w;
    float ar = 0.f, az = 0.f, an = 0.f;
    for (int k = 0; k < 16; k++) {
        int j = lane + 32 * k;
        float h = sx[j];
        ar = fmaf(Wih2[(size_t)i * HD + j], h, ar);
        az = fmaf(Wih2[(size_t)(512 + i) * HD + j], h, az);
        an = fmaf(Wih2[(size_t)(1024 + i) * HD + j], h, an);
    }
    ar = wredu(ar); az = wredu(az); an = wredu(an);
    if (lane == 0) {
        float r = sigf(ar + bih2[i] + bhh2[i]);
        float z = sigf(az + bih2[512 + i] + bhh2[512 + i]);
        float n = tanha(an + bih2[1024 + i] + r * bhh2[1024 + i]);
        g_h1[i] = (1.0f - z) * n;
    }
}

// ---------------------------------------------------------------------------
// Tail B: sentence-GRU step 2 (input hidden_y, h_prev = h1). 128 CTAs x 128.
// ---------------------------------------------------------------------------
__global__ void __launch_bounds__(128) tailB(const float* __restrict__ Wih2,
                                             const float* __restrict__ Whh2,
                                             const float* __restrict__ bih2,
                                             const float* __restrict__ bhh2) {
    __shared__ float sy[HD], s1[HD];
    const int tid = threadIdx.x, w = tid >> 5, lane = tid & 31;
    for (int i = tid; i < HD; i += 128) {
        sy[i] = __uint_as_float((unsigned)g_htag[0][1][i]);
        s1[i] = g_h1[i];
    }
    __syncthreads();

    const int i = blockIdx.x * 4 + w;
    float ir = 0.f, iz = 0.f, in_ = 0.f, hr = 0.f, hz = 0.f, hn_ = 0.f;
    for (int k = 0; k < 16; k++) {
        int j = lane + 32 * k;
        float hy = sy[j], h1 = s1[j];
        size_t r0 = (size_t)i * HD + j;
        size_t r1 = (size_t)(512 + i) * HD + j;
        size_t r2 = (size_t)(1024 + i) * HD + j;
        ir = fmaf(Wih2[r0], hy, ir);   hr = fmaf(Whh2[r0], h1, hr);
        iz = fmaf(Wih2[r1], hy, iz);   hz = fmaf(Whh2[r1], h1, hz);
        in_ = fmaf(Wih2[r2], hy, in_); hn_ = fmaf(Whh2[r2], h1, hn_);
    }
    ir = wredu(ir); iz = wredu(iz); in_ = wredu(in_);
    hr = wredu(hr); hz = wredu(hz); hn_ = wredu(hn_);
    if (lane == 0) {
        float r = sigf(ir + bih2[i] + hr + bhh2[i]);
        float z = sigf(iz + bih2[512 + i] + hz + bhh2[512 + i]);
        float n = tanha(in_ + bih2[1024 + i] + r * (hn_ + bhh2[1024 + i]));
        g_h2[i] = n + z * (s1[i] - n);
    }
}

// ---------------------------------------------------------------------------
// Tail C: MLP + log_softmax. 1 CTA x 1024.
// ---------------------------------------------------------------------------
__global__ void __launch_bounds__(1024) tailC(const float* __restrict__ W1,
                                              const float* __restrict__ b1,
                                              const float* __restrict__ W2,
                                              const float* __restrict__ b2,
                                              float* __restrict__ out) {
    __shared__ float s2[HD], m1[128];
    const int tid = threadIdx.x, w = tid >> 5, lane = tid & 31;
    if (tid < HD) s2[tid] = g_h2[tid];
    __syncthreads();

    const int r0 = w * 4;
    float acc[4] = {0.f, 0.f, 0.f, 0.f};
    for (int k = 0; k < 16; k++) {
        int j = lane + 32 * k;
        float h = s2[j];
#pragma unroll
        for (int q = 0; q < 4; q++)
            acc[q] = fmaf(W1[(size_t)(r0 + q) * HD + j], h, acc[q]);
    }
#pragma unroll
    for (int q = 0; q < 4; q++) acc[q] = wredu(acc[q]);
    if (lane == 0) {
#pragma unroll
        for (int q = 0; q < 4; q++)
            m1[r0 + q] = fmaxf(acc[q] + b1[r0 + q], 0.0f);
    }
    __syncthreads();

    if (w == 0) {
        float a0 = 0.f, a1 = 0.f;
        for (int k = 0; k < 4; k++) {
            int j = lane + 32 * k;
            a0 = fmaf(W2[j], m1[j], a0);
            a1 = fmaf(W2[128 + j], m1[j], a1);
        }
        a0 = wredu(a0);
        a1 = wredu(a1);
        if (lane == 0) {
            float v0 = fmaxf(a0 + b2[0], 0.0f);
            float v1 = fmaxf(a1 + b2[1], 0.0f);
            float m = fmaxf(v0, v1);
            float lse = m + logf(expf(v0 - m) + expf(v1 - m));
            out[0] = v0 - lse;
            out[1] = v1 - lse;
        }
    }
}

// ---------------------------------------------------------------------------
extern "C" void kernel_launch(void* const* d_in, const int* in_sizes, int n_in,
                              void* d_out, int out_size) {
    const int*   x    = (const int*)d_in[0];
    const int*   y    = (const int*)d_in[1];
    const float* emb  = (const float*)d_in[2];
    const float* Wih1 = (const float*)d_in[3];
    const float* Whh1 = (const float*)d_in[4];
    const float* bih1 = (const float*)d_in[5];
    const float* bhh1 = (const float*)d_in[6];
    const float* Wih2 = (const float*)d_in[7];
    const float* Whh2 = (const float*)d_in[8];
    const float* bih2 = (const float*)d_in[9];
    const float* bhh2 = (const float*)d_in[10];
    const float* W1   = (const float*)d_in[11];
    const float* b1   = (const float*)d_in[12];
    const float* W2   = (const float*)d_in[13];
    const float* b2   = (const float*)d_in[14];
    float* out = (float*)d_out;

    init_kernel<<<2, 1024>>>();
    fused_kernel<<<REC_CTAS + GEMM_CTAS, 512>>>(x, y, emb, Wih1, bih1, Whh1, bhh1,
                                                Wih2, Whh2, W1);
    tailA<<<128, 128>>>(Wih2, bih2, bhh2);
    tailB<<<128, 128>>>(Wih2, Whh2, bih2, bhh2);
    tailC<<<1, 1024>>>(W1, b1, W2, b2, out);
}

// round 11
// speedup vs baseline: 1.9330x; 1.3516x over previous
#include <cuda_runtime.h>
#include <cstdint>

#define HD   512
#define SEQT 4096
#define G3   1536
#define REC_CTAS 128           // 64 per sequence
#define GEMM_CTAS 20
#define NUNITS (GEMM_CTAS * 2)
#define NTILES (128 * 24)

// ---------------- static device scratch (no cudaMalloc allowed) -------------
__device__ __align__(16) float g_GI[2][SEQT][G3];   // precomputed input gates (~50MB)
__device__ unsigned long long g_htag[2][2][HD];     // {tag,val}, [buf][seq][i]
__device__ unsigned g_cnt[128];                     // per row-tile completion counters
__device__ float g_h1[HD], g_h2[HD];                // sentence-GRU intermediates
__device__ float g_sink;                            // prefetch sink (never read)

// ---------------- memory helpers --------------------------------------------
__device__ __forceinline__ unsigned ld_acq_u32(const unsigned* p) {
    unsigned v; asm volatile("ld.acquire.gpu.global.u32 %0,[%1];" : "=r"(v) : "l"(p)); return v;
}
__device__ __forceinline__ void red_rel_add(unsigned* p, unsigned v) {
    asm volatile("red.release.gpu.global.add.u32 [%0],%1;" :: "l"(p), "r"(v) : "memory");
}
__device__ __forceinline__ unsigned long long ld_rlx_u64(const unsigned long long* p) {
    unsigned long long v; asm volatile("ld.relaxed.gpu.global.b64 %0,[%1];" : "=l"(v) : "l"(p)); return v;
}
__device__ __forceinline__ void st_rlx_u64(unsigned long long* p, unsigned long long v) {
    asm volatile("st.relaxed.gpu.global.b64 [%0],%1;" :: "l"(p), "l"(v) : "memory");
}
__device__ __forceinline__ void fence_gpu() {
    asm volatile("fence.acq_rel.gpu;" ::: "memory");
}
__device__ __forceinline__ void bar_named(int id, int cnt) {
    asm volatile("bar.sync %0, %1;" :: "r"(id), "r"(cnt) : "memory");
}

// HW tanh (MUFU.TANH) — validated rel_err 0.0 since R4
__device__ __forceinline__ float tanha(float x) {
    float y; asm("tanh.approx.f32 %0,%1;" : "=f"(y) : "f"(x)); return y;
}
__device__ __forceinline__ float sigf(float x) {       // sig(x)=0.5*tanh(x/2)+0.5
    return fmaf(0.5f, tanha(0.5f * x), 0.5f);
}
__device__ __forceinline__ float wredu(float v) {
#pragma unroll
    for (int o = 16; o; o >>= 1) v += __shfl_xor_sync(0xffffffffu, v, o);
    return v;
}

// ---------------------------------------------------------------------------
// Dummy kernel: two no-op launches shift fused_kernel to launch index 5 so
// ncu's "-s 5 -c 1" captures the kernel that is 99% of runtime.
// ---------------------------------------------------------------------------
__global__ void dummy_kernel() {}

// ---------------------------------------------------------------------------
// Kernel 0: reset tags + GI counters (runs every graph replay)
// ---------------------------------------------------------------------------
__global__ void init_kernel() {
    int i = blockIdx.x * blockDim.x + threadIdx.x;
    if (i < 2 * 2 * HD) ((unsigned long long*)g_htag)[i] = 0ull;   // tag 0 never matches
    if (i < 128) g_cnt[i] = 0u;
}

// ---------------------------------------------------------------------------
// Fused kernel: 148 CTAs x 512 threads.  (R8 frozen topology — every
// deviation from this exchange structure has regressed: R5, R6, R7, R9, R10.)
//   CTAs [0,128):  persistent GRU recurrence:
//                  seq = bx>>6, c = bx&63 owns h[8c..8c+8).
//                  Every thread polls ONE 8B tag word (simple dependent spin
//                  — queue-minimal, validated optimal in R10 post-mortem).
//                  Warps 0-11: 2 gate rows each, vectorized LDS.128 dot.
//                  Publish: warp0 lanes 0-7, ONE coalesced 64B store.
//   CTAs [128,148): 2 x 256-thread GEMM units each, producing GI row-tiles,
//                  then prefetching tail weights into L2.
// ---------------------------------------------------------------------------
__global__ void __launch_bounds__(512, 1)
fused_kernel(const int* __restrict__ xs, const int* __restrict__ ys,
             const float* __restrict__ emb,
             const float* __restrict__ Wih, const float* __restrict__ bih,
             const float* __restrict__ Whh, const float* __restrict__ bhh,
             const float* __restrict__ Wih2, const float* __restrict__ Whh2,
             const float* __restrict__ W1) {
    const int tid = threadIdx.x;

    if (blockIdx.x >= REC_CTAS) {
        // ================== GEMM producer (R8, unchanged) ==================
        __shared__ __align__(16) float pool[2 * 2048];
        const int gidx = tid >> 8;            // 0..1
        const int tidl = tid & 255;
        const int barid = gidx + 1;           // named barriers 1..2
        float* As = pool + gidx * 2048;
        float* Bs = As + 1024;

        const int tr = (tidl >> 4) << 2;
        const int tc = (tidl & 15) << 2;
        const int lr = tidl >> 2;
        const int kv = (tidl & 3) << 2;

        const int unit = (blockIdx.x - REC_CTAS) * 2 + gidx;

        for (int T = unit; T < NTILES; T += NUNITS) {
            const int e  = T / 24;
            const int cc = T - e * 24;
            const int xy = e & 1;
            const int trow = (e >> 1) << 6;
            const int col0 = cc << 6;

            const int tok = (xy ? ys : xs)[trow + lr];
            const float* arow = emb + (size_t)tok * HD;
            const float* brow = Wih + (size_t)(col0 + lr) * HD;

            float acc[4][4];
#pragma unroll
            for (int i = 0; i < 4; i++)
#pragma unroll
                for (int j = 0; j < 4; j++) acc[i][j] = 0.0f;

            for (int k0 = 0; k0 < HD; k0 += 16) {
                float4 a4 = *(const float4*)(arow + k0 + kv);
                float4 b4 = *(const float4*)(brow + k0 + kv);
                As[(kv + 0) * 64 + lr] = a4.x; As[(kv + 1) * 64 + lr] = a4.y;
                As[(kv + 2) * 64 + lr] = a4.z; As[(kv + 3) * 64 + lr] = a4.w;
                Bs[(kv + 0) * 64 + lr] = b4.x; Bs[(kv + 1) * 64 + lr] = b4.y;
                Bs[(kv + 2) * 64 + lr] = b4.z; Bs[(kv + 3) * 64 + lr] = b4.w;
                bar_named(barid, 256);
#pragma unroll
                for (int k = 0; k < 16; k++) {
                    float4 av = *(const float4*)&As[k * 64 + tr];
                    float4 bv = *(const float4*)&Bs[k * 64 + tc];
                    acc[0][0] = fmaf(av.x, bv.x, acc[0][0]);
                    acc[0][1] = fmaf(av.x, bv.y, acc[0][1]);
                    acc[0][2] = fmaf(av.x, bv.z, acc[0][2]);
                    acc[0][3] = fmaf(av.x, bv.w, acc[0][3]);
                    acc[1][0] = fmaf(av.y, bv.x, acc[1][0]);
                    acc[1][1] = fmaf(av.y, bv.y, acc[1][1]);
                    acc[1][2] = fmaf(av.y, bv.z, acc[1][2]);
                    acc[1][3] = fmaf(av.y, bv.w, acc[1][3]);
                    acc[2][0] = fmaf(av.z, bv.x, acc[2][0]);
                    acc[2][1] = fmaf(av.z, bv.y, acc[2][1]);
                    acc[2][2] = fmaf(av.z, bv.z, acc[2][2]);
                    acc[2][3] = fmaf(av.z, bv.w, acc[2][3]);
                    acc[3][0] = fmaf(av.w, bv.x, acc[3][0]);
                    acc[3][1] = fmaf(av.w, bv.y, acc[3][1]);
                    acc[3][2] = fmaf(av.w, bv.z, acc[3][2]);
                    acc[3][3] = fmaf(av.w, bv.w, acc[3][3]);
                }
                bar_named(barid, 256);
            }

            float4 bias = *(const float4*)(bih + col0 + tc);
#pragma unroll
            for (int ii = 0; ii < 4; ii++) {
                float4 v;
                v.x = acc[ii][0] + bias.x;
                v.y = acc[ii][1] + bias.y;
                v.z = acc[ii][2] + bias.z;
                v.w = acc[ii][3] + bias.w;
                *(float4*)&g_GI[xy][trow + tr + ii][col0 + tc] = v;
            }
            bar_named(barid, 256);
            if (tidl == 0) {
                fence_gpu();
                red_rel_add(&g_cnt[e], 1u);
            }
        }

        // ---- warm L2 with tail weights
        {
            const int nthr = GEMM_CTAS * 512;
            const int gt = (blockIdx.x - REC_CTAS) * 512 + tid;
            float s = 0.0f;
            const int n4 = (G3 * HD) / 4;
            for (int i = gt; i < n4; i += nthr) {
                float4 a = __ldcg((const float4*)Wih2 + i);
                float4 b = __ldcg((const float4*)Whh2 + i);
                s += a.x + a.w + b.x + b.w;
            }
            const int m4 = (128 * HD) / 4;
            for (int i = gt; i < m4; i += nthr) {
                float4 a = __ldcg((const float4*)W1 + i);
                s += a.x + a.w;
            }
            if (s == 1.2345678e38f) g_sink = s;    // never true; defeats DCE
        }
        return;
    }

    // ================== GRU recurrence (one sequence per CTA group) =========
    const int seq = blockIdx.x >> 6;          // 0 = x, 1 = y
    const int c   = blockIdx.x & 63;          // owns h indices [8c, 8c+8)
    const int w    = tid >> 5;                // 16 warps
    const int lane = tid & 31;

    __shared__ __align__(16) float sm_h[HD];
    __shared__ float sm_gh[24];

    // dot warps (w < 12): rows lr0=2w, lr1=2w+1 of 24 (row lr: gate lr>>3,
    // local h idx lr&7). Weight mapping matches the float4 h read:
    // lane covers h columns 4*lane+128*k+e (k=0..3, e=0..3).
    const int lr0 = 2 * w, lr1 = 2 * w + 1;
    const int g0r = ((lr0 >> 3) << 9) + (c << 3) + (lr0 & 7);
    const int g1r = ((lr1 >> 3) << 9) + (c << 3) + (lr1 & 7);

    float wa[16], wb[16];
    float bh0 = 0.f, bh1 = 0.f;
    if (w < 12) {
#pragma unroll
        for (int k = 0; k < 4; k++) {
            float4 va = *(const float4*)&Whh[(size_t)g0r * HD + 4 * lane + 128 * k];
            float4 vb = *(const float4*)&Whh[(size_t)g1r * HD + 4 * lane + 128 * k];
            wa[4 * k + 0] = va.x; wa[4 * k + 1] = va.y;
            wa[4 * k + 2] = va.z; wa[4 * k + 3] = va.w;
            wb[4 * k + 0] = vb.x; wb[4 * k + 1] = vb.y;
            wb[4 * k + 2] = vb.z; wb[4 * k + 3] = vb.w;
        }
        bh0 = bhh[g0r];
        bh1 = bhh[g1r];
    }
    const int i8 = (c << 3) + tid;            // owned h index (tid < 8)

    for (int t = 0; t < SEQT; t++) {
        // ---- GI readiness (one counter for this seq, every 64 steps) ----
        if ((t & 63) == 0) {
            if (tid == 0) {
                const int e = ((t >> 6) << 1) + seq;
                while (ld_acq_u32(&g_cnt[e]) < 24u) { }
            }
            __syncthreads();
        }

        // ---- GI prefetch (latency hides under the h poll) ----
        float gr, gz, gn;
        if (tid < 8) {
            const float* GI = &g_GI[seq][t][0];
            gr = GI[i8]; gz = GI[512 + i8]; gn = GI[1024 + i8];
        }

        // ---- stage h: exactly one tag word per thread, dependent spin ----
        {
            float hv;
            if (t == 0) {
                hv = 0.0f;
            } else {
                const unsigned long long* pp = &g_htag[t & 1][seq][tid];
                unsigned long long a = ld_rlx_u64(pp);
                while ((unsigned)(a >> 32) != (unsigned)t) a = ld_rlx_u64(pp);
                hv = __uint_as_float((unsigned)a);
            }
            sm_h[tid] = hv;
        }
        __syncthreads();                       // (A)

        // ---- gate threads: prefetch own h early (off the gate chain) ----
        float hold = 0.0f;
        if (tid < 8) hold = sm_h[i8];

        // ---- 2 gate rows per warp, vectorized h reads ----
        if (w < 12) {
            const float4* hb4 = (const float4*)sm_h;
            float a0 = 0.f, a1 = 0.f;
#pragma unroll
            for (int k = 0; k < 4; k++) {
                float4 h4 = hb4[lane + 32 * k];
                a0 = fmaf(wa[4 * k + 0], h4.x, a0);
                a1 = fmaf(wb[4 * k + 0], h4.x, a1);
                a0 = fmaf(wa[4 * k + 1], h4.y, a0);
                a1 = fmaf(wb[4 * k + 1], h4.y, a1);
                a0 = fmaf(wa[4 * k + 2], h4.z, a0);
                a1 = fmaf(wb[4 * k + 2], h4.z, a1);
                a0 = fmaf(wa[4 * k + 3], h4.w, a0);
                a1 = fmaf(wb[4 * k + 3], h4.w, a1);
            }
#pragma unroll
            for (int o = 16; o; o >>= 1) {
                a0 += __shfl_xor_sync(0xffffffffu, a0, o);
                a1 += __shfl_xor_sync(0xffffffffu, a1, o);
            }
            if (lane == 0) {
                sm_gh[lr0] = a0 + bh0;
                sm_gh[lr1] = a1 + bh1;
            }
        }
        __syncthreads();                       // (B)

        // ---- gates + publish: warp 0 lanes 0-7, ONE coalesced 64B store ----
        if (tid < 8) {
            float r = sigf(gr + sm_gh[tid]);
            float z = sigf(gz + sm_gh[8 + tid]);
            float n = tanha(gn + r * sm_gh[16 + tid]);
            float hn = n + z * (hold - n);
            st_rlx_u64(&g_htag[(t + 1) & 1][seq][i8],
                       (((unsigned long long)(unsigned)(t + 1)) << 32) |
                       (unsigned long long)__float_as_uint(hn));
        }
        // Hazard proof (identical to R8):
        //  - sm_h overwrites at t+1 happen after bar(B,t); all reads of
        //    sm_h(t) (dot + hold prefetch) precede bar(B,t).
        //  - sm_gh(t) reads by gate threads precede their own arrival at
        //    bar(A,t+1), which gates any sm_gh rewrite.
    }
}

// ---------------------------------------------------------------------------
// Tail A: sentence-GRU step 1 (input hidden_x, h_prev = 0). 128 CTAs x 128.
// ---------------------------------------------------------------------------
__global__ void __launch_bounds__(128) tailA(const float* __restrict__ Wih2,
                                             const float* __restrict__ bih2,
                                             const float* __restrict__ bhh2) {
    __shared__ float sx[HD];
    const int tid = threadIdx.x, w = tid >> 5, lane = tid & 31;
    for (int i = tid; i < HD; i += 128)
        sx[i] = __uint_as_float((unsigned)g_htag[0][0][i]);
    __syncthreads();

    const int i = blockIdx.x * 4 + w;
    float ar = 0.f, az = 0.f, an = 0.f;
    for (int k = 0; k < 16; k++) {
        int j = lane + 32 * k;
        float h = sx[j];
        ar = fmaf(Wih2[(size_t)i * HD + j], h, ar);
        az = fmaf(Wih2[(size_t)(512 + i) * HD + j], h, az);
        an = fmaf(Wih2[(size_t)(1024 + i) * HD + j], h, an);
    }
    ar = wredu(ar); az = wredu(az); an = wredu(an);
    if (lane == 0) {
        float r = sigf(ar + bih2[i] + bhh2[i]);
        float z = sigf(az + bih2[512 + i] + bhh2[512 + i]);
        float n = tanha(an + bih2[1024 + i] + r * bhh2[1024 + i]);
        g_h1[i] = (1.0f - z) * n;
    }
}

// ---------------------------------------------------------------------------
// Tail B: sentence-GRU step 2 (input hidden_y, h_prev = h1). 128 CTAs x 128.
// ---------------------------------------------------------------------------
__global__ void __launch_bounds__(128) tailB(const float* __restrict__ Wih2,
                                             const float* __restrict__ Whh2,
                                             const float* __restrict__ bih2,
                                             const float* __restrict__ bhh2) {
    __shared__ float sy[HD], s1[HD];
    const int tid = threadIdx.x, w = tid >> 5, lane = tid & 31;
    for (int i = tid; i < HD; i += 128) {
        sy[i] = __uint_as_float((unsigned)g_htag[0][1][i]);
        s1[i] = g_h1[i];
    }
    __syncthreads();

    const int i = blockIdx.x * 4 + w;
    float ir = 0.f, iz = 0.f, in_ = 0.f, hr = 0.f, hz = 0.f, hn_ = 0.f;
    for (int k = 0; k < 16; k++) {
        int j = lane + 32 * k;
        float hy = sy[j], h1 = s1[j];
        size_t r0 = (size_t)i * HD + j;
        size_t r1 = (size_t)(512 + i) * HD + j;
        size_t r2 = (size_t)(1024 + i) * HD + j;
        ir = fmaf(Wih2[r0], hy, ir);   hr = fmaf(Whh2[r0], h1, hr);
        iz = fmaf(Wih2[r1], hy, iz);   hz = fmaf(Whh2[r1], h1, hz);
        in_ = fmaf(Wih2[r2], hy, in_); hn_ = fmaf(Whh2[r2], h1, hn_);
    }
    ir = wredu(ir); iz = wredu(iz); in_ = wredu(in_);
    hr = wredu(hr); hz = wredu(hz); hn_ = wredu(hn_);
    if (lane == 0) {
        float r = sigf(ir + bih2[i] + hr + bhh2[i]);
        float z = sigf(iz + bih2[512 + i] + hz + bhh2[512 + i]);
        float n = tanha(in_ + bih2[1024 + i] + r * (hn_ + bhh2[1024 + i]));
        g_h2[i] = n + z * (s1[i] - n);
    }
}

// ---------------------------------------------------------------------------
// Tail C: MLP + log_softmax. 1 CTA x 1024.
// ---------------------------------------------------------------------------
__global__ void __launch_bounds__(1024) tailC(const float* __restrict__ W1,
                                              const float* __restrict__ b1,
                                              const float* __restrict__ W2,
                                              const float* __restrict__ b2,
                                              float* __restrict__ out) {
    __shared__ float s2[HD], m1[128];
    const int tid = threadIdx.x, w = tid >> 5, lane = tid & 31;
    if (tid < HD) s2[tid] = g_h2[tid];
    __syncthreads();

    const int r0 = w * 4;
    float acc[4] = {0.f, 0.f, 0.f, 0.f};
    for (int k = 0; k < 16; k++) {
        int j = lane + 32 * k;
        float h = s2[j];
#pragma unroll
        for (int q = 0; q < 4; q++)
            acc[q] = fmaf(W1[(size_t)(r0 + q) * HD + j], h, acc[q]);
    }
#pragma unroll
    for (int q = 0; q < 4; q++) acc[q] = wredu(acc[q]);
    if (lane == 0) {
#pragma unroll
        for (int q = 0; q < 4; q++)
            m1[r0 + q] = fmaxf(acc[q] + b1[r0 + q], 0.0f);
    }
    __syncthreads();

    if (w == 0) {
        float a0 = 0.f, a1 = 0.f;
        for (int k = 0; k < 4; k++) {
            int j = lane + 32 * k;
            a0 = fmaf(W2[j], m1[j], a0);
            a1 = fmaf(W2[128 + j], m1[j], a1);
        }
        a0 = wredu(a0);
        a1 = wredu(a1);
        if (lane == 0) {
            float v0 = fmaxf(a0 + b2[0], 0.0f);
            float v1 = fmaxf(a1 + b2[1], 0.0f);
            float m = fmaxf(v0, v1);
            float lse = m + logf(expf(v0 - m) + expf(v1 - m));
            out[0] = v0 - lse;
            out[1] = v1 - lse;
        }
    }
}

// ---------------------------------------------------------------------------
extern "C" void kernel_launch(void* const* d_in, const int* in_sizes, int n_in,
                              void* d_out, int out_size) {
    const int*   x    = (const int*)d_in[0];
    const int*   y    = (const int*)d_in[1];
    const float* emb  = (const float*)d_in[2];
    const float* Wih1 = (const float*)d_in[3];
    const float* Whh1 = (const float*)d_in[4];
    const float* bih1 = (const float*)d_in[5];
    const float* bhh1 = (const float*)d_in[6];
    const float* Wih2 = (const float*)d_in[7];
    const float* Whh2 = (const float*)d_in[8];
    const float* bih2 = (const float*)d_in[9];
    const float* bhh2 = (const float*)d_in[10];
    const float* W1   = (const float*)d_in[11];
    const float* b1   = (const float*)d_in[12];
    const float* W2   = (const float*)d_in[13];
    const float* b2   = (const float*)d_in[14];
    float* out = (float*)d_out;

    // Two no-op launches: shifts fused_kernel to launch index 5 so the ncu
    // capture ("-s 5 -c 1") profiles the kernel that is ~99% of runtime.
    dummy_kernel<<<1, 32>>>();
    dummy_kernel<<<1, 32>>>();
    init_kernel<<<2, 1024>>>();
    fused_kernel<<<REC_CTAS + GEMM_CTAS, 512>>>(x, y, emb, Wih1, bih1, Whh1, bhh1,
                                                Wih2, Whh2, W1);
    tailA<<<128, 128>>>(Wih2, bih2, bhh2);
    tailB<<<128, 128>>>(Wih2, Whh2, bih2, bhh2);
    tailC<<<1, 1024>>>(W1, b1, W2, b2, out);
}